// round 6
// baseline (speedup 1.0000x reference)
#include <cuda_runtime.h>
#include <cuda_bf16.h>
#include <math.h>
#include <stdint.h>

// ---------------------------------------------------------------------------
// CortexBlock on GB300 (compute_103 pipeline => mma.sync HMMA path)
// B=4, T=2048, D=1024, H=16, Dh=64, R=16
// GEMMs: bf16x2 error-compensated (hi*hi + hi*lo + lo*hi), fp32 accumulate.
// K-chunk 32, 2-stage cp.async pipeline, 80B smem row stride -> 2 CTAs/SM.
// ---------------------------------------------------------------------------

#define D_MODEL 1024
#define N_HEADS 16
#define D_HEAD  64
#define RANK    16
#define DECAY   0.95f
#define ALPHA_MAX 0.05f
#define BETA    0.01f

#define BB 4
#define TT 2048
#define BT (BB*TT)   // 8192

// ---------------- scratch (static device globals; no allocs allowed) -------
__device__ __align__(256) __nv_bfloat16 g_xhi[BT * D_MODEL];
__device__ __align__(256) __nv_bfloat16 g_xlo[BT * D_MODEL];
__device__ __align__(256) __nv_bfloat16 g_whi[4 * D_MODEL * D_MODEL];  // Wq,Wk,Wv,Wo
__device__ __align__(256) __nv_bfloat16 g_wlo[4 * D_MODEL * D_MODEL];
__device__ __align__(256) __nv_bfloat16 g_yhi[BT * D_MODEL];
__device__ __align__(256) __nv_bfloat16 g_ylo[BT * D_MODEL];
__device__ __align__(256) float g_q[BT * D_MODEL];
__device__ __align__(256) float g_k[BT * D_MODEL];
__device__ __align__(256) float g_v[BT * D_MODEL];
__device__ __align__(256) float g_alpha[BT * N_HEADS];

// ---------------- small asm helpers ----------------------------------------
__device__ __forceinline__ uint32_t smem_u32(const void* p) {
    uint32_t a;
    asm("{ .reg .u64 t; cvta.to.shared.u64 t, %1; cvt.u32.u64 %0, t; }"
        : "=r"(a) : "l"(p));
    return a;
}
__device__ __forceinline__ void cp_async16(uint32_t daddr, const void* gaddr) {
    asm volatile("cp.async.cg.shared.global [%0], [%1], 16;"
                 :: "r"(daddr), "l"(gaddr) : "memory");
}
#define CP_COMMIT()  asm volatile("cp.async.commit_group;" ::: "memory")
#define CP_WAIT(n)   asm volatile("cp.async.wait_group %0;" :: "n"(n) : "memory")

__device__ __forceinline__ void ldsm_x4(uint32_t (&r)[4], uint32_t addr) {
    asm volatile("ldmatrix.sync.aligned.m8n8.x4.shared.b16 {%0,%1,%2,%3}, [%4];"
                 : "=r"(r[0]), "=r"(r[1]), "=r"(r[2]), "=r"(r[3]) : "r"(addr));
}
__device__ __forceinline__ void mma_16816(float (&d)[4], const uint32_t (&a)[4],
                                          uint32_t b0, uint32_t b1) {
    asm volatile(
        "mma.sync.aligned.m16n8k16.row.col.f32.bf16.bf16.f32 "
        "{%0,%1,%2,%3}, {%4,%5,%6,%7}, {%8,%9}, {%0,%1,%2,%3};"
        : "+f"(d[0]), "+f"(d[1]), "+f"(d[2]), "+f"(d[3])
        : "r"(a[0]), "r"(a[1]), "r"(a[2]), "r"(a[3]), "r"(b0), "r"(b1));
}

// ---------------------------------------------------------------------------
// Fused bf16x2 GEMM: C = Ahi*Bhi^T + Ahi*Blo^T + Alo*Bhi^T  (fp32 out)
// CTA tile 128x128, K-chunk 32. Per chunk: 4 tiles (Ahi,Alo,Bhi,Blo) loaded
// once; 3 MMA passes. 8 warps = 2(m) x 4(n) of 64x32 warp tiles.
// 2-stage cp.async pipeline, 2 CTAs/SM (80KB smem), stride 40 halves (80B).
// ---------------------------------------------------------------------------
#define GM 128
#define GN 128
#define GKC 32
#define AST 40                            // halves per smem row (80B)
#define TILE_HALVES (GM * AST)            // 5120 halves = 10240 B
#define STAGE_HALVES (4 * TILE_HALVES)    // 4 tiles per stage
#define STAGE_BYTES (STAGE_HALVES * 2)    // 40960
#define GEMM_SMEM_BYTES (2 * STAGE_BYTES) // 81920

__global__ __launch_bounds__(256, 2) void gemm_bf16x2(
    const __nv_bfloat16* __restrict__ Ahi, const __nv_bfloat16* __restrict__ Alo,
    const __nv_bfloat16* __restrict__ Whi, const __nv_bfloat16* __restrict__ Wlo,
    float* __restrict__ C0, float* __restrict__ C1, float* __restrict__ C2,
    int M, int N, int K)
{
    extern __shared__ __nv_bfloat16 smem[];

    const int tid  = threadIdx.x;
    const int wid  = tid >> 5;
    const int lane = tid & 31;
    const int rowBase = blockIdx.y * GM;
    const int colBase = blockIdx.x * GN;
    const int z = blockIdx.z;

    const __nv_bfloat16* Bhi = Whi + (size_t)z * D_MODEL * D_MODEL;
    const __nv_bfloat16* Blo = Wlo + (size_t)z * D_MODEL * D_MODEL;
    float* C = (z == 0) ? C0 : (z == 1) ? C1 : C2;

    const int wm = (wid >> 2) * 64;
    const int wn = (wid & 3) * 32;

    const uint32_t smBase = smem_u32(smem);

    float acc[4][4][4];
#pragma unroll
    for (int i = 0; i < 4; i++)
#pragma unroll
        for (int j = 0; j < 4; j++)
#pragma unroll
            for (int c = 0; c < 4; c++) acc[i][j][c] = 0.0f;

    const int aRow = lane & 15;
    const int aKo  = (lane >> 4) * 8;
    const int bNo  = ((lane >> 4) << 3) + (lane & 7);
    const int bKo  = ((lane >> 3) & 1) * 8;

    const int NCH = K / GKC;              // 32

    // load all 4 tiles for chunk ci: 128 rows x 64B per tile = 2 x 16B / thread
    auto issue = [&](int ci) {
        const int k0 = ci * GKC;
        const uint32_t stage = smBase + (uint32_t)(ci & 1) * STAGE_BYTES;
#pragma unroll
        for (int i = 0; i < 2; i++) {
            int L = tid + (i << 8);           // 0..511
            int row = L >> 2;
            int seg = L & 3;                  // 16B segment in 64B row
            uint32_t off = (uint32_t)row * (AST * 2) + seg * 16;
            const size_t ga = (size_t)(rowBase + row) * K + k0 + seg * 8;
            const size_t gb = (size_t)(colBase + row) * K + k0 + seg * 8;
            cp_async16(stage + 0 * (TILE_HALVES * 2) + off, Ahi + ga);
            cp_async16(stage + 1 * (TILE_HALVES * 2) + off, Alo + ga);
            cp_async16(stage + 2 * (TILE_HALVES * 2) + off, Bhi + gb);
            cp_async16(stage + 3 * (TILE_HALVES * 2) + off, Blo + gb);
        }
        CP_COMMIT();
    };

    issue(0);
    issue(1);

    for (int ci = 0; ci < NCH; ci++) {
        CP_WAIT(1);                       // chunk ci arrived
        __syncthreads();

        const uint32_t stage = smBase + (uint32_t)(ci & 1) * STAGE_BYTES;

#pragma unroll
        for (int pass = 0; pass < 3; pass++) {
            const uint32_t aBase = stage + (pass == 2 ? 1u : 0u) * (TILE_HALVES * 2);
            const uint32_t bBase = stage + (pass == 1 ? 3u : 2u) * (TILE_HALVES * 2);
#pragma unroll
            for (int ks = 0; ks < 2; ks++) {  // 2 x k16 per 32-chunk
                uint32_t Ar[4][4];
#pragma unroll
                for (int mi = 0; mi < 4; mi++) {
                    uint32_t addr = aBase + (uint32_t)(wm + mi * 16 + aRow) * (AST * 2)
                                  + (uint32_t)(ks * 16 + aKo) * 2;
                    ldsm_x4(Ar[mi], addr);
                }
                uint32_t Br[2][4];
#pragma unroll
                for (int ni = 0; ni < 2; ni++) {
                    uint32_t addr = bBase + (uint32_t)(wn + ni * 16 + bNo) * (AST * 2)
                                  + (uint32_t)(ks * 16 + bKo) * 2;
                    ldsm_x4(Br[ni], addr);
                }
#pragma unroll
                for (int mi = 0; mi < 4; mi++)
#pragma unroll
                    for (int j = 0; j < 4; j++)
                        mma_16816(acc[mi][j], Ar[mi],
                                  Br[j >> 1][(j & 1) * 2], Br[j >> 1][(j & 1) * 2 + 1]);
            }
        }

        __syncthreads();                  // all warps done reading this stage
        if (ci + 2 < NCH) issue(ci + 2);  // refill the stage just vacated
        else CP_COMMIT();                 // keep group counting correct
    }

    // epilogue
#pragma unroll
    for (int mi = 0; mi < 4; mi++) {
        const int row0 = rowBase + wm + mi * 16 + (lane >> 2);
#pragma unroll
        for (int j = 0; j < 4; j++) {
            const int col = colBase + wn + j * 8 + (lane & 3) * 2;
            *reinterpret_cast<float2*>(C + (size_t)row0 * N + col) =
                make_float2(acc[mi][j][0], acc[mi][j][1]);
            *reinterpret_cast<float2*>(C + (size_t)(row0 + 8) * N + col) =
                make_float2(acc[mi][j][2], acc[mi][j][3]);
        }
    }
}

// ---------------------------------------------------------------------------
// Fused x-split + alpha. Block = 16 rows, 512 threads (16 warps = 16 heads).
// ---------------------------------------------------------------------------
__global__ __launch_bounds__(512) void splitx_alpha_kernel(
    const float* __restrict__ x, const float* __restrict__ Wa,
    const float* __restrict__ ba, const float* __restrict__ m_gate,
    const float* __restrict__ ascale,
    __nv_bfloat16* __restrict__ xhi, __nv_bfloat16* __restrict__ xlo,
    float* __restrict__ alpha)
{
    extern __shared__ float xs[];        // [16][1024]
    const int tid  = threadIdx.x;
    const int warp = tid >> 5;           // head
    const int lane = tid & 31;
    const int rowBase = blockIdx.x * 16;

    const float4* xg = reinterpret_cast<const float4*>(x + (size_t)rowBase * D_MODEL);
#pragma unroll
    for (int it = 0; it < 8; it++) {
        int i = tid + it * 512;
        float4 v = xg[i];
        reinterpret_cast<float4*>(xs)[i] = v;
        __nv_bfloat16 h0 = __float2bfloat16(v.x);
        __nv_bfloat16 h1 = __float2bfloat16(v.y);
        __nv_bfloat16 h2 = __float2bfloat16(v.z);
        __nv_bfloat16 h3 = __float2bfloat16(v.w);
        __nv_bfloat162* ph = reinterpret_cast<__nv_bfloat162*>(
            xhi + (size_t)rowBase * D_MODEL + i * 4);
        __nv_bfloat162* pl = reinterpret_cast<__nv_bfloat162*>(
            xlo + (size_t)rowBase * D_MODEL + i * 4);
        ph[0] = __nv_bfloat162(h0, h1);
        ph[1] = __nv_bfloat162(h2, h3);
        pl[0] = __nv_bfloat162(__float2bfloat16(v.x - __bfloat162float(h0)),
                               __float2bfloat16(v.y - __bfloat162float(h1)));
        pl[1] = __nv_bfloat162(__float2bfloat16(v.z - __bfloat162float(h2)),
                               __float2bfloat16(v.w - __bfloat162float(h3)));
    }
    __syncthreads();

    float wa[32];
#pragma unroll
    for (int i = 0; i < 32; i++)
        wa[i] = Wa[(size_t)warp * D_MODEL + i * 32 + lane];
    const float bw = ba[warp];

#pragma unroll 4
    for (int row = 0; row < 16; row++) {
        const float* xr = xs + row * D_MODEL;
        float s = 0.0f;
#pragma unroll
        for (int i = 0; i < 32; i++)
            s = fmaf(wa[i], xr[i * 32 + lane], s);
#pragma unroll
        for (int off = 16; off; off >>= 1)
            s += __shfl_xor_sync(0xFFFFFFFFu, s, off);
        if (lane == 0) {
            const int r = rowBase + row;
            float sg = __fdividef(1.0f, 1.0f + __expf(-(s + bw)));
            float a = sg * m_gate[r] * ascale[(size_t)r * N_HEADS + warp];
            alpha[(size_t)r * N_HEADS + warp] = fminf(a, ALPHA_MAX);
        }
    }
}

// ---------------------------------------------------------------------------
// Weight splits, all 4 matrices in one launch. DW = 1<<20 elements each.
// ---------------------------------------------------------------------------
__global__ __launch_bounds__(256) void split4_kernel(
    const float* __restrict__ W0, const float* __restrict__ W1,
    const float* __restrict__ W2, const float* __restrict__ W3,
    __nv_bfloat16* __restrict__ hi, __nv_bfloat16* __restrict__ lo)
{
    const int i = blockIdx.x * 256 + threadIdx.x;       // 0 .. 4M-1
    const int sel = i >> 20;
    const int off = i & ((1 << 20) - 1);
    const float* src = (sel == 0) ? W0 : (sel == 1) ? W1 : (sel == 2) ? W2 : W3;
    float v = src[off];
    __nv_bfloat16 h = __float2bfloat16(v);
    hi[i] = h;
    lo[i] = __float2bfloat16(v - __bfloat162float(h));
}

// ---------------------------------------------------------------------------
// Sequential fast-weight scan; 1 barrier/step (score combine of step t-1 is
// piggybacked on step t's barrier; y(t-1) stored during step t).
// Block = (b,h); 64 threads (thread = d).
// ---------------------------------------------------------------------------
__global__ __launch_bounds__(64) void scan_kernel(
    const float* __restrict__ q, const float* __restrict__ k,
    const float* __restrict__ v, const float* __restrict__ alpha,
    __nv_bfloat16* __restrict__ yhi, __nv_bfloat16* __restrict__ ylo, int T)
{
    const int bh = blockIdx.x;
    const int b = bh / N_HEADS;
    const int h = bh % N_HEADS;
    const int d = threadIdx.x;
    const int warp = d >> 5;
    const int lane = d & 31;

    float U[RANK], Vv[RANK];
#pragma unroll
    for (int r = 0; r < RANK; r++) { U[r] = 0.0f; Vv[r] = 0.0f; }

    __shared__ float  sm_ku[2][16][2];   // [buf][r][warp]
    __shared__ float2 sm_sc[2][2];       // [buf][warp] = (s0,s1) partials

    const int l4 = lane & 15;
    const int rIdx = ((l4 & 1) << 3) | ((l4 & 2) << 1) | ((l4 & 4) >> 1) | ((l4 & 8) >> 3);

    const size_t strideT = (size_t)N_HEADS * D_HEAD;   // 1024
    size_t idx = ((size_t)b * T * N_HEADS + h) * D_HEAD + d;
    const size_t abase = (size_t)b * T * N_HEADS + h;

    float qt = q[idx], kt = k[idx], vt = v[idx];
    float a  = alpha[abase];

    float sp0 = 0.f, sp1 = 0.f;
    float vprev = 0.f, kfprev = 0.f;
    size_t idxprev = idx;

    for (int t = 0; t < T; t++) {
        const int buf = t & 1;
        const size_t nidx = idx + strideT;
        float nq = 0.f, nk = 0.f, nv = 0.f, na = 0.f;
        if (t + 1 < T) {
            nq = q[nidx]; nk = k[nidx]; nv = v[nidx];
            na = alpha[abase + (size_t)(t + 1) * N_HEADS];
        }

        float p[RANK];
#pragma unroll
        for (int r = 0; r < RANK; r++) {
            U[r]  *= DECAY;
            Vv[r] *= DECAY;
            p[r] = kt * U[r];
        }

#pragma unroll
        for (int s = 1, cnt = 8; s <= 8; s <<= 1, cnt >>= 1) {
            const bool hi = (lane & s) != 0;
#pragma unroll
            for (int i = 0; i < cnt; i++) {
                float lo_v = p[i], hi_v = p[i + cnt];
                float send = hi ? lo_v : hi_v;
                float recv = __shfl_xor_sync(0xFFFFFFFFu, send, s);
                p[i] = (hi ? hi_v : lo_v) + recv;
            }
        }
        float vr = p[0] + __shfl_xor_sync(0xFFFFFFFFu, p[0], 16);

        sm_ku[buf][rIdx][warp] = vr;
        if (lane == 0) sm_sc[buf][warp] = make_float2(sp0, sp1);
        __syncthreads();

        float ku[RANK];
#pragma unroll
        for (int r = 0; r < RANK; r++) {
            float2 t2 = *reinterpret_cast<const float2*>(&sm_ku[buf][r][0]);
            ku[r] = t2.x + t2.y;
        }

        const float ak = a * kt;
        const float av = a * vt;
        float kf = 0.0f;
#pragma unroll
        for (int r = 0; r < RANK; r++) {
            float u = fmaf(ak, ku[r], U[r]);
            float w = fmaf(av, ku[r], Vv[r]);
            u -= BETA * fminf(fmaxf(u, -1.0f), 1.0f);
            w -= BETA * fminf(fmaxf(w, -1.0f), 1.0f);
            U[r] = u;
            Vv[r] = w;
            kf = fmaf(u, w, kf);
        }

        if (t > 0) {
            float2 w0 = sm_sc[buf][0];
            float2 w1 = sm_sc[buf][1];
            const float S0 = w0.x + w1.x;
            const float S1 = w0.y + w1.y;
            const float m1 = __fdividef(1.0f, 1.0f + __expf(S0 - S1));
            const float yv = (1.0f - m1) * vprev + m1 * kfprev;
            const __nv_bfloat16 hb = __float2bfloat16(yv);
            yhi[idxprev] = hb;
            ylo[idxprev] = __float2bfloat16(yv - __bfloat162float(hb));
        }

        const float qn = qt * 0.125f;
        float s0 = qn * kt;
        float s1 = qn * kf;
#pragma unroll
        for (int off = 16; off; off >>= 1) {
            s0 += __shfl_xor_sync(0xFFFFFFFFu, s0, off);
            s1 += __shfl_xor_sync(0xFFFFFFFFu, s1, off);
        }
        sp0 = s0; sp1 = s1;
        vprev = vt; kfprev = kf; idxprev = idx;

        qt = nq; kt = nk; vt = nv; a = na;
        idx = nidx;
    }

    if (lane == 0) sm_sc[T & 1][warp] = make_float2(sp0, sp1);
    __syncthreads();
    {
        float2 w0 = sm_sc[T & 1][0];
        float2 w1 = sm_sc[T & 1][1];
        const float S0 = w0.x + w1.x;
        const float S1 = w0.y + w1.y;
        const float m1 = __fdividef(1.0f, 1.0f + __expf(S0 - S1));
        const float yv = (1.0f - m1) * vprev + m1 * kfprev;
        const __nv_bfloat16 hb = __float2bfloat16(yv);
        yhi[idxprev] = hb;
        ylo[idxprev] = __float2bfloat16(yv - __bfloat162float(hb));
    }
}

// ---------------------------------------------------------------------------
// Launch
// ---------------------------------------------------------------------------
extern "C" void kernel_launch(void* const* d_in, const int* in_sizes, int n_in,
                              void* d_out, int out_size)
{
    const float* x      = (const float*)d_in[0];
    const float* m_gate = (const float*)d_in[1];
    const float* ascale = (const float*)d_in[2];
    const float* Wq     = (const float*)d_in[3];
    const float* Wk     = (const float*)d_in[4];
    const float* Wv     = (const float*)d_in[5];
    const float* Wo     = (const float*)d_in[6];
    const float* Wa     = (const float*)d_in[7];
    const float* ba     = (const float*)d_in[8];
    // d_in[9] = mix_logit: cancels in the 2-way softmax; unused.
    float* out = (float*)d_out;

    const int M = in_sizes[1] > 0 ? in_sizes[1] : BT;  // B*T
    const int T = M / BB;

    __nv_bfloat16 *xhi, *xlo, *whi, *wlo, *yhi, *ylo;
    float *dq, *dk, *dv, *da;
    cudaGetSymbolAddress((void**)&xhi, g_xhi);
    cudaGetSymbolAddress((void**)&xlo, g_xlo);
    cudaGetSymbolAddress((void**)&whi, g_whi);
    cudaGetSymbolAddress((void**)&wlo, g_wlo);
    cudaGetSymbolAddress((void**)&yhi, g_yhi);
    cudaGetSymbolAddress((void**)&ylo, g_ylo);
    cudaGetSymbolAddress((void**)&dq, g_q);
    cudaGetSymbolAddress((void**)&dk, g_k);
    cudaGetSymbolAddress((void**)&dv, g_v);
    cudaGetSymbolAddress((void**)&da, g_alpha);

    const int DW = D_MODEL * D_MODEL;

    static bool attr_set = false;
    if (!attr_set) {
        cudaFuncSetAttribute(gemm_bf16x2,
                             cudaFuncAttributeMaxDynamicSharedMemorySize, GEMM_SMEM_BYTES);
        cudaFuncSetAttribute(splitx_alpha_kernel,
                             cudaFuncAttributeMaxDynamicSharedMemorySize, 16 * D_MODEL * 4);
        attr_set = true;
    }

    splitx_alpha_kernel<<<M / 16, 512, 16 * D_MODEL * 4>>>(
        x, Wa, ba, m_gate, ascale, xhi, xlo, da);

    split4_kernel<<<(4 * DW) / 256, 256>>>(Wq, Wk, Wv, Wo, whi, wlo);

    dim3 gqkv(D_MODEL / GN, M / GM, 3);
    gemm_bf16x2<<<gqkv, 256, GEMM_SMEM_BYTES>>>(xhi, xlo, whi, wlo,
                                                dq, dk, dv, M, D_MODEL, D_MODEL);

    scan_kernel<<<BB * N_HEADS, 64>>>(dq, dk, dv, da, yhi, ylo, T);

    dim3 go(D_MODEL / GN, M / GM, 1);
    gemm_bf16x2<<<go, 256, GEMM_SMEM_BYTES>>>(yhi, ylo, whi + 3 * DW, wlo + 3 * DW,
                                              out, out, out, M, D_MODEL, D_MODEL);
}

// round 7
// speedup vs baseline: 1.1032x; 1.1032x over previous
#include <cuda_runtime.h>
#include <cuda_fp16.h>
#include <math.h>
#include <stdint.h>

// ---------------------------------------------------------------------------
// CortexBlock on GB300 (compute_103 pipeline => mma.sync HMMA path)
// B=4, T=2048, D=1024, H=16, Dh=64, R=16
// GEMMs: fp16 2-pass error compensation: C = (Ahi + Alo) * W^T, W rounded to
// fp16 once (error 2^-12). 33% fewer MMAs than the bf16 3-pass scheme.
// ---------------------------------------------------------------------------

#define D_MODEL 1024
#define N_HEADS 16
#define D_HEAD  64
#define RANK    16
#define DECAY   0.95f
#define ALPHA_MAX 0.05f
#define BETA    0.01f

#define BB 4
#define TT 2048
#define BT (BB*TT)   // 8192

// ---------------- scratch (static device globals; no allocs allowed) -------
__device__ __align__(256) __half g_xhi[BT * D_MODEL];
__device__ __align__(256) __half g_xlo[BT * D_MODEL];
__device__ __align__(256) __half g_w[4 * D_MODEL * D_MODEL];   // Wq,Wk,Wv,Wo fp16
__device__ __align__(256) __half g_yhi[BT * D_MODEL];
__device__ __align__(256) __half g_ylo[BT * D_MODEL];
__device__ __align__(256) float g_q[BT * D_MODEL];
__device__ __align__(256) float g_k[BT * D_MODEL];
__device__ __align__(256) float g_v[BT * D_MODEL];
__device__ __align__(256) float g_alpha[BT * N_HEADS];

// ---------------- small asm helpers ----------------------------------------
__device__ __forceinline__ uint32_t smem_u32(const void* p) {
    uint32_t a;
    asm("{ .reg .u64 t; cvta.to.shared.u64 t, %1; cvt.u32.u64 %0, t; }"
        : "=r"(a) : "l"(p));
    return a;
}
__device__ __forceinline__ void cp_async16(uint32_t daddr, const void* gaddr) {
    asm volatile("cp.async.cg.shared.global [%0], [%1], 16;"
                 :: "r"(daddr), "l"(gaddr) : "memory");
}
#define CP_COMMIT()  asm volatile("cp.async.commit_group;" ::: "memory")
#define CP_WAIT(n)   asm volatile("cp.async.wait_group %0;" :: "n"(n) : "memory")

__device__ __forceinline__ void ldsm_x4(uint32_t (&r)[4], uint32_t addr) {
    asm volatile("ldmatrix.sync.aligned.m8n8.x4.shared.b16 {%0,%1,%2,%3}, [%4];"
                 : "=r"(r[0]), "=r"(r[1]), "=r"(r[2]), "=r"(r[3]) : "r"(addr));
}
__device__ __forceinline__ void mma_16816_f16(float (&d)[4], const uint32_t (&a)[4],
                                              uint32_t b0, uint32_t b1) {
    asm volatile(
        "mma.sync.aligned.m16n8k16.row.col.f32.f16.f16.f32 "
        "{%0,%1,%2,%3}, {%4,%5,%6,%7}, {%8,%9}, {%0,%1,%2,%3};"
        : "+f"(d[0]), "+f"(d[1]), "+f"(d[2]), "+f"(d[3])
        : "r"(a[0]), "r"(a[1]), "r"(a[2]), "r"(a[3]), "r"(b0), "r"(b1));
}

// ---------------------------------------------------------------------------
// fp16 2-pass GEMM: C[M,N](fp32) = (Ahi + Alo)[M,K] * W[N,K]^T
// CTA tile 128x128, K-chunk 64. Per chunk: 3 tiles (Ahi, Alo, W) loaded once;
// 2 MMA passes. 8 warps = 2(m) x 4(n) of 64x32 warp tiles.
// 3-stage cp.async pipeline, 1 barrier per chunk. smem stride 72 halves.
// ---------------------------------------------------------------------------
#define GM 128
#define GN 128
#define GKC 64
#define AST 72
#define TILE_HALVES (GM * AST)            // 9216 halves = 18432 B
#define TILE_BYTES  (TILE_HALVES * 2)
#define STAGE_BYTES (3 * TILE_BYTES)      // 55296
#define GEMM_SMEM_BYTES (3 * STAGE_BYTES) // 165888

__global__ __launch_bounds__(256, 1) void gemm_f16_2p(
    const __half* __restrict__ Ahi, const __half* __restrict__ Alo,
    const __half* __restrict__ Wbase,
    float* __restrict__ C0, float* __restrict__ C1, float* __restrict__ C2,
    int M, int N, int K)
{
    extern __shared__ __half smem[];

    const int tid  = threadIdx.x;
    const int wid  = tid >> 5;
    const int lane = tid & 31;
    const int rowBase = blockIdx.y * GM;
    const int colBase = blockIdx.x * GN;
    const int z = blockIdx.z;

    const __half* Bw = Wbase + (size_t)z * D_MODEL * D_MODEL;
    float* C = (z == 0) ? C0 : (z == 1) ? C1 : C2;

    const int wm = (wid >> 2) * 64;
    const int wn = (wid & 3) * 32;

    const uint32_t smBase = smem_u32(smem);

    float acc[4][4][4];
#pragma unroll
    for (int i = 0; i < 4; i++)
#pragma unroll
        for (int j = 0; j < 4; j++)
#pragma unroll
            for (int c = 0; c < 4; c++) acc[i][j][c] = 0.0f;

    const int aRow = lane & 15;
    const int aKo  = (lane >> 4) * 8;
    const int bNo  = ((lane >> 4) << 3) + (lane & 7);
    const int bKo  = ((lane >> 3) & 1) * 8;

    const int NCH = K / GKC;              // 16

    auto issue = [&](int ci) {
        const int k0 = ci * GKC;
        const uint32_t stage = smBase + (uint32_t)(ci % 3) * STAGE_BYTES;
#pragma unroll
        for (int i = 0; i < 4; i++) {
            int L = tid + (i << 8);           // 0..1023
            int row = L >> 3;
            int seg = L & 7;                  // 16B segment in 128B row
            uint32_t off = (uint32_t)row * (AST * 2) + seg * 16;
            const size_t ga = (size_t)(rowBase + row) * K + k0 + seg * 8;
            const size_t gb = (size_t)(colBase + row) * K + k0 + seg * 8;
            cp_async16(stage + 0 * TILE_BYTES + off, Ahi + ga);
            cp_async16(stage + 1 * TILE_BYTES + off, Alo + ga);
            cp_async16(stage + 2 * TILE_BYTES + off, Bw  + gb);
        }
        CP_COMMIT();
    };

    issue(0);
    issue(1);

    for (int ci = 0; ci < NCH; ci++) {
        CP_WAIT(1);                       // chunk ci complete
        __syncthreads();
        if (ci + 2 < NCH) issue(ci + 2);
        else CP_COMMIT();                 // keep group counting correct

        const uint32_t stage = smBase + (uint32_t)(ci % 3) * STAGE_BYTES;
        const uint32_t bBase0 = stage + 2 * TILE_BYTES;

#pragma unroll
        for (int pass = 0; pass < 2; pass++) {
            const uint32_t aBase = stage + (uint32_t)pass * TILE_BYTES;
#pragma unroll
            for (int ks = 0; ks < 4; ks++) {
                uint32_t Ar[4][4];
#pragma unroll
                for (int mi = 0; mi < 4; mi++) {
                    uint32_t addr = aBase + (uint32_t)(wm + mi * 16 + aRow) * (AST * 2)
                                  + (uint32_t)(ks * 16 + aKo) * 2;
                    ldsm_x4(Ar[mi], addr);
                }
                uint32_t Br[2][4];
#pragma unroll
                for (int ni = 0; ni < 2; ni++) {
                    uint32_t addr = bBase0 + (uint32_t)(wn + ni * 16 + bNo) * (AST * 2)
                                  + (uint32_t)(ks * 16 + bKo) * 2;
                    ldsm_x4(Br[ni], addr);
                }
#pragma unroll
                for (int mi = 0; mi < 4; mi++)
#pragma unroll
                    for (int j = 0; j < 4; j++)
                        mma_16816_f16(acc[mi][j], Ar[mi],
                                      Br[j >> 1][(j & 1) * 2], Br[j >> 1][(j & 1) * 2 + 1]);
            }
        }
    }

    // epilogue
#pragma unroll
    for (int mi = 0; mi < 4; mi++) {
        const int row0 = rowBase + wm + mi * 16 + (lane >> 2);
#pragma unroll
        for (int j = 0; j < 4; j++) {
            const int col = colBase + wn + j * 8 + (lane & 3) * 2;
            *reinterpret_cast<float2*>(C + (size_t)row0 * N + col) =
                make_float2(acc[mi][j][0], acc[mi][j][1]);
            *reinterpret_cast<float2*>(C + (size_t)(row0 + 8) * N + col) =
                make_float2(acc[mi][j][2], acc[mi][j][3]);
        }
    }
}

// ---------------------------------------------------------------------------
// Fused x-split(fp16 hi/lo) + alpha. Block = 16 rows, 512 threads (16 heads).
// ---------------------------------------------------------------------------
__global__ __launch_bounds__(512) void splitx_alpha_kernel(
    const float* __restrict__ x, const float* __restrict__ Wa,
    const float* __restrict__ ba, const float* __restrict__ m_gate,
    const float* __restrict__ ascale,
    __half* __restrict__ xhi, __half* __restrict__ xlo,
    float* __restrict__ alpha)
{
    extern __shared__ float xs[];        // [16][1024]
    const int tid  = threadIdx.x;
    const int warp = tid >> 5;           // head
    const int lane = tid & 31;
    const int rowBase = blockIdx.x * 16;

    const float4* xg = reinterpret_cast<const float4*>(x + (size_t)rowBase * D_MODEL);
#pragma unroll
    for (int it = 0; it < 8; it++) {
        int i = tid + it * 512;
        float4 v = xg[i];
        reinterpret_cast<float4*>(xs)[i] = v;
        __half h0 = __float2half_rn(v.x);
        __half h1 = __float2half_rn(v.y);
        __half h2 = __float2half_rn(v.z);
        __half h3 = __float2half_rn(v.w);
        __half2* ph = reinterpret_cast<__half2*>(xhi + (size_t)rowBase * D_MODEL + i * 4);
        __half2* pl = reinterpret_cast<__half2*>(xlo + (size_t)rowBase * D_MODEL + i * 4);
        ph[0] = __half2(h0, h1);
        ph[1] = __half2(h2, h3);
        pl[0] = __half2(__float2half_rn(v.x - __half2float(h0)),
                        __float2half_rn(v.y - __half2float(h1)));
        pl[1] = __half2(__float2half_rn(v.z - __half2float(h2)),
                        __float2half_rn(v.w - __half2float(h3)));
    }
    __syncthreads();

    float wa[32];
#pragma unroll
    for (int i = 0; i < 32; i++)
        wa[i] = Wa[(size_t)warp * D_MODEL + i * 32 + lane];
    const float bw = ba[warp];

#pragma unroll 4
    for (int row = 0; row < 16; row++) {
        const float* xr = xs + row * D_MODEL;
        float s = 0.0f;
#pragma unroll
        for (int i = 0; i < 32; i++)
            s = fmaf(wa[i], xr[i * 32 + lane], s);
#pragma unroll
        for (int off = 16; off; off >>= 1)
            s += __shfl_xor_sync(0xFFFFFFFFu, s, off);
        if (lane == 0) {
            const int r = rowBase + row;
            float sg = __fdividef(1.0f, 1.0f + __expf(-(s + bw)));
            float a = sg * m_gate[r] * ascale[(size_t)r * N_HEADS + warp];
            alpha[(size_t)r * N_HEADS + warp] = fminf(a, ALPHA_MAX);
        }
    }
}

// ---------------------------------------------------------------------------
// Round all 4 weight matrices to fp16 in one launch. DW = 1<<20 elems each.
// ---------------------------------------------------------------------------
__global__ __launch_bounds__(256) void cvt4_kernel(
    const float* __restrict__ W0, const float* __restrict__ W1,
    const float* __restrict__ W2, const float* __restrict__ W3,
    __half* __restrict__ out)
{
    const int i = blockIdx.x * 256 + threadIdx.x;       // 0 .. 4M-1
    const int sel = i >> 20;
    const int off = i & ((1 << 20) - 1);
    const float* src = (sel == 0) ? W0 : (sel == 1) ? W1 : (sel == 2) ? W2 : W3;
    out[i] = __float2half_rn(src[off]);
}

// ---------------------------------------------------------------------------
// Sequential fast-weight scan; 1 barrier/step; y -> fp16 hi/lo outputs.
// Block = (b,h); 64 threads (thread = d).
// ---------------------------------------------------------------------------
__global__ __launch_bounds__(64) void scan_kernel(
    const float* __restrict__ q, const float* __restrict__ k,
    const float* __restrict__ v, const float* __restrict__ alpha,
    __half* __restrict__ yhi, __half* __restrict__ ylo, int T)
{
    const int bh = blockIdx.x;
    const int b = bh / N_HEADS;
    const int h = bh % N_HEADS;
    const int d = threadIdx.x;
    const int warp = d >> 5;
    const int lane = d & 31;

    float U[RANK], Vv[RANK];
#pragma unroll
    for (int r = 0; r < RANK; r++) { U[r] = 0.0f; Vv[r] = 0.0f; }

    __shared__ float  sm_ku[2][16][2];   // [buf][r][warp]
    __shared__ float2 sm_sc[2][2];       // [buf][warp] = (s0,s1) partials

    const int l4 = lane & 15;
    const int rIdx = ((l4 & 1) << 3) | ((l4 & 2) << 1) | ((l4 & 4) >> 1) | ((l4 & 8) >> 3);

    const size_t strideT = (size_t)N_HEADS * D_HEAD;   // 1024
    size_t idx = ((size_t)b * T * N_HEADS + h) * D_HEAD + d;
    const size_t abase = (size_t)b * T * N_HEADS + h;

    float qt = q[idx], kt = k[idx], vt = v[idx];
    float a  = alpha[abase];

    float sp0 = 0.f, sp1 = 0.f;
    float vprev = 0.f, kfprev = 0.f;
    size_t idxprev = idx;

    for (int t = 0; t < T; t++) {
        const int buf = t & 1;
        const size_t nidx = idx + strideT;
        float nq = 0.f, nk = 0.f, nv = 0.f, na = 0.f;
        if (t + 1 < T) {
            nq = q[nidx]; nk = k[nidx]; nv = v[nidx];
            na = alpha[abase + (size_t)(t + 1) * N_HEADS];
        }

        float p[RANK];
#pragma unroll
        for (int r = 0; r < RANK; r++) {
            U[r]  *= DECAY;
            Vv[r] *= DECAY;
            p[r] = kt * U[r];
        }

#pragma unroll
        for (int s = 1, cnt = 8; s <= 8; s <<= 1, cnt >>= 1) {
            const bool hi = (lane & s) != 0;
#pragma unroll
            for (int i = 0; i < cnt; i++) {
                float lo_v = p[i], hi_v = p[i + cnt];
                float send = hi ? lo_v : hi_v;
                float recv = __shfl_xor_sync(0xFFFFFFFFu, send, s);
                p[i] = (hi ? hi_v : lo_v) + recv;
            }
        }
        float vr = p[0] + __shfl_xor_sync(0xFFFFFFFFu, p[0], 16);

        sm_ku[buf][rIdx][warp] = vr;
        if (lane == 0) sm_sc[buf][warp] = make_float2(sp0, sp1);
        __syncthreads();

        float ku[RANK];
#pragma unroll
        for (int r = 0; r < RANK; r++) {
            float2 t2 = *reinterpret_cast<const float2*>(&sm_ku[buf][r][0]);
            ku[r] = t2.x + t2.y;
        }

        const float ak = a * kt;
        const float av = a * vt;
        float kf = 0.0f;
#pragma unroll
        for (int r = 0; r < RANK; r++) {
            float u = fmaf(ak, ku[r], U[r]);
            float w = fmaf(av, ku[r], Vv[r]);
            u -= BETA * fminf(fmaxf(u, -1.0f), 1.0f);
            w -= BETA * fminf(fmaxf(w, -1.0f), 1.0f);
            U[r] = u;
            Vv[r] = w;
            kf = fmaf(u, w, kf);
        }

        if (t > 0) {
            float2 w0 = sm_sc[buf][0];
            float2 w1 = sm_sc[buf][1];
            const float S0 = w0.x + w1.x;
            const float S1 = w0.y + w1.y;
            const float m1 = __fdividef(1.0f, 1.0f + __expf(S0 - S1));
            const float yv = (1.0f - m1) * vprev + m1 * kfprev;
            const __half hb = __float2half_rn(yv);
            yhi[idxprev] = hb;
            ylo[idxprev] = __float2half_rn(yv - __half2float(hb));
        }

        const float qn = qt * 0.125f;
        float s0 = qn * kt;
        float s1 = qn * kf;
#pragma unroll
        for (int off = 16; off; off >>= 1) {
            s0 += __shfl_xor_sync(0xFFFFFFFFu, s0, off);
            s1 += __shfl_xor_sync(0xFFFFFFFFu, s1, off);
        }
        sp0 = s0; sp1 = s1;
        vprev = vt; kfprev = kf; idxprev = idx;

        qt = nq; kt = nk; vt = nv; a = na;
        idx = nidx;
    }

    if (lane == 0) sm_sc[T & 1][warp] = make_float2(sp0, sp1);
    __syncthreads();
    {
        float2 w0 = sm_sc[T & 1][0];
        float2 w1 = sm_sc[T & 1][1];
        const float S0 = w0.x + w1.x;
        const float S1 = w0.y + w1.y;
        const float m1 = __fdividef(1.0f, 1.0f + __expf(S0 - S1));
        const float yv = (1.0f - m1) * vprev + m1 * kfprev;
        const __half hb = __float2half_rn(yv);
        yhi[idxprev] = hb;
        ylo[idxprev] = __float2half_rn(yv - __half2float(hb));
    }
}

// ---------------------------------------------------------------------------
// Launch
// ---------------------------------------------------------------------------
extern "C" void kernel_launch(void* const* d_in, const int* in_sizes, int n_in,
                              void* d_out, int out_size)
{
    const float* x      = (const float*)d_in[0];
    const float* m_gate = (const float*)d_in[1];
    const float* ascale = (const float*)d_in[2];
    const float* Wq     = (const float*)d_in[3];
    const float* Wk     = (const float*)d_in[4];
    const float* Wv     = (const float*)d_in[5];
    const float* Wo     = (const float*)d_in[6];
    const float* Wa     = (const float*)d_in[7];
    const float* ba     = (const float*)d_in[8];
    // d_in[9] = mix_logit: cancels in the 2-way softmax; unused.
    float* out = (float*)d_out;

    const int M = in_sizes[1] > 0 ? in_sizes[1] : BT;  // B*T
    const int T = M / BB;

    __half *xhi, *xlo, *wf, *yhi, *ylo;
    float *dq, *dk, *dv, *da;
    cudaGetSymbolAddress((void**)&xhi, g_xhi);
    cudaGetSymbolAddress((void**)&xlo, g_xlo);
    cudaGetSymbolAddress((void**)&wf,  g_w);
    cudaGetSymbolAddress((void**)&yhi, g_yhi);
    cudaGetSymbolAddress((void**)&ylo, g_ylo);
    cudaGetSymbolAddress((void**)&dq, g_q);
    cudaGetSymbolAddress((void**)&dk, g_k);
    cudaGetSymbolAddress((void**)&dv, g_v);
    cudaGetSymbolAddress((void**)&da, g_alpha);

    const int DW = D_MODEL * D_MODEL;

    static bool attr_set = false;
    if (!attr_set) {
        cudaFuncSetAttribute(gemm_f16_2p,
                             cudaFuncAttributeMaxDynamicSharedMemorySize, GEMM_SMEM_BYTES);
        cudaFuncSetAttribute(splitx_alpha_kernel,
                             cudaFuncAttributeMaxDynamicSharedMemorySize, 16 * D_MODEL * 4);
        attr_set = true;
    }

    splitx_alpha_kernel<<<M / 16, 512, 16 * D_MODEL * 4>>>(
        x, Wa, ba, m_gate, ascale, xhi, xlo, da);

    cvt4_kernel<<<(4 * DW) / 256, 256>>>(Wq, Wk, Wv, Wo, wf);

    dim3 gqkv(D_MODEL / GN, M / GM, 3);
    gemm_f16_2p<<<gqkv, 256, GEMM_SMEM_BYTES>>>(xhi, xlo, wf,
                                                dq, dk, dv, M, D_MODEL, D_MODEL);

    scan_kernel<<<BB * N_HEADS, 64>>>(dq, dk, dv, da, yhi, ylo, T);

    dim3 go(D_MODEL / GN, M / GM, 1);
    gemm_f16_2p<<<go, 256, GEMM_SMEM_BYTES>>>(yhi, ylo, wf + (size_t)3 * DW,
                                              out, out, out, M, D_MODEL, D_MODEL);
}

// round 8
// speedup vs baseline: 1.3219x; 1.1983x over previous
#include <cuda_runtime.h>
#include <cuda_fp16.h>
#include <math.h>
#include <stdint.h>

// ---------------------------------------------------------------------------
// CortexBlock on GB300 (compute_103 pipeline => mma.sync HMMA path)
// B=4, T=2048, D=1024, H=16, Dh=64, R=16
// GEMMs: single-pass fp16 (fp32 accumulate). HMMA-issue-bound => minimize MMAs.
// ---------------------------------------------------------------------------

#define D_MODEL 1024
#define N_HEADS 16
#define D_HEAD  64
#define RANK    16
#define DECAY   0.95f
#define ALPHA_MAX 0.05f
#define BETA    0.01f

#define BB 4
#define TT 2048
#define BT (BB*TT)   // 8192

// ---------------- scratch (static device globals; no allocs allowed) -------
__device__ __align__(256) __half g_xh[BT * D_MODEL];
__device__ __align__(256) __half g_w[4 * D_MODEL * D_MODEL];   // Wq,Wk,Wv,Wo fp16
__device__ __align__(256) __half g_yh[BT * D_MODEL];
__device__ __align__(256) float g_q[BT * D_MODEL];
__device__ __align__(256) float g_k[BT * D_MODEL];
__device__ __align__(256) float g_v[BT * D_MODEL];
__device__ __align__(256) float g_alpha[BT * N_HEADS];

// ---------------- small asm helpers ----------------------------------------
__device__ __forceinline__ uint32_t smem_u32(const void* p) {
    uint32_t a;
    asm("{ .reg .u64 t; cvta.to.shared.u64 t, %1; cvt.u32.u64 %0, t; }"
        : "=r"(a) : "l"(p));
    return a;
}
__device__ __forceinline__ void cp_async16(uint32_t daddr, const void* gaddr) {
    asm volatile("cp.async.cg.shared.global [%0], [%1], 16;"
                 :: "r"(daddr), "l"(gaddr) : "memory");
}
#define CP_COMMIT()  asm volatile("cp.async.commit_group;" ::: "memory")
#define CP_WAIT(n)   asm volatile("cp.async.wait_group %0;" :: "n"(n) : "memory")

__device__ __forceinline__ void ldsm_x4(uint32_t (&r)[4], uint32_t addr) {
    asm volatile("ldmatrix.sync.aligned.m8n8.x4.shared.b16 {%0,%1,%2,%3}, [%4];"
                 : "=r"(r[0]), "=r"(r[1]), "=r"(r[2]), "=r"(r[3]) : "r"(addr));
}
__device__ __forceinline__ void mma_16816_f16(float (&d)[4], const uint32_t (&a)[4],
                                              uint32_t b0, uint32_t b1) {
    asm volatile(
        "mma.sync.aligned.m16n8k16.row.col.f32.f16.f16.f32 "
        "{%0,%1,%2,%3}, {%4,%5,%6,%7}, {%8,%9}, {%0,%1,%2,%3};"
        : "+f"(d[0]), "+f"(d[1]), "+f"(d[2]), "+f"(d[3])
        : "r"(a[0]), "r"(a[1]), "r"(a[2]), "r"(a[3]), "r"(b0), "r"(b1));
}

// ---------------------------------------------------------------------------
// fp16 single-pass GEMM: C[M,N](fp32) = A[M,K] * W[N,K]^T
// CTA tile 128x128, K-chunk 64, 2 tiles (A, W) per chunk.
// 8 warps = 2(m) x 4(n) of 64x32 warp tiles.
// 4-stage cp.async pipeline (3 chunks in flight), 1 barrier per chunk.
// smem row stride 72 halves (144B): conflict-free ldmatrix.
// ---------------------------------------------------------------------------
#define GM 128
#define GN 128
#define GKC 64
#define AST 72
#define TILE_HALVES (GM * AST)            // 9216 halves = 18432 B
#define TILE_BYTES  (TILE_HALVES * 2)
#define STAGE_BYTES (2 * TILE_BYTES)      // 36864
#define NSTAGE 4
#define GEMM_SMEM_BYTES (NSTAGE * STAGE_BYTES)   // 147456

__global__ __launch_bounds__(256, 1) void gemm_f16(
    const __half* __restrict__ A, const __half* __restrict__ Wbase,
    float* __restrict__ C0, float* __restrict__ C1, float* __restrict__ C2,
    int M, int N, int K)
{
    extern __shared__ __half smem[];

    const int tid  = threadIdx.x;
    const int wid  = tid >> 5;
    const int lane = tid & 31;
    const int rowBase = blockIdx.y * GM;
    const int colBase = blockIdx.x * GN;
    const int z = blockIdx.z;

    const __half* Bw = Wbase + (size_t)z * D_MODEL * D_MODEL;
    float* C = (z == 0) ? C0 : (z == 1) ? C1 : C2;

    const int wm = (wid >> 2) * 64;
    const int wn = (wid & 3) * 32;

    const uint32_t smBase = smem_u32(smem);

    float acc[4][4][4];
#pragma unroll
    for (int i = 0; i < 4; i++)
#pragma unroll
        for (int j = 0; j < 4; j++)
#pragma unroll
            for (int c = 0; c < 4; c++) acc[i][j][c] = 0.0f;

    const int aRow = lane & 15;
    const int aKo  = (lane >> 4) * 8;
    const int bNo  = ((lane >> 4) << 3) + (lane & 7);
    const int bKo  = ((lane >> 3) & 1) * 8;

    const int NCH = K / GKC;              // 16

    auto issue = [&](int ci) {
        const int k0 = ci * GKC;
        const uint32_t stage = smBase + (uint32_t)(ci % NSTAGE) * STAGE_BYTES;
#pragma unroll
        for (int i = 0; i < 4; i++) {
            int L = tid + (i << 8);           // 0..1023
            int row = L >> 3;
            int seg = L & 7;                  // 16B segment in 128B row
            uint32_t off = (uint32_t)row * (AST * 2) + seg * 16;
            cp_async16(stage + off,
                       A + (size_t)(rowBase + row) * K + k0 + seg * 8);
            cp_async16(stage + TILE_BYTES + off,
                       Bw + (size_t)(colBase + row) * K + k0 + seg * 8);
        }
        CP_COMMIT();
    };

    issue(0);
    issue(1);
    issue(2);

    for (int ci = 0; ci < NCH; ci++) {
        CP_WAIT(2);                       // chunk ci complete (2 newer pending)
        __syncthreads();
        if (ci + 3 < NCH) issue(ci + 3);  // refill stage (ci+3)%4
        else CP_COMMIT();                 // keep group counting correct

        const uint32_t stage  = smBase + (uint32_t)(ci % NSTAGE) * STAGE_BYTES;
        const uint32_t bBase0 = stage + TILE_BYTES;

#pragma unroll
        for (int ks = 0; ks < 4; ks++) {
            uint32_t Ar[4][4];
#pragma unroll
            for (int mi = 0; mi < 4; mi++) {
                uint32_t addr = stage + (uint32_t)(wm + mi * 16 + aRow) * (AST * 2)
                              + (uint32_t)(ks * 16 + aKo) * 2;
                ldsm_x4(Ar[mi], addr);
            }
            uint32_t Br[2][4];
#pragma unroll
            for (int ni = 0; ni < 2; ni++) {
                uint32_t addr = bBase0 + (uint32_t)(wn + ni * 16 + bNo) * (AST * 2)
                              + (uint32_t)(ks * 16 + bKo) * 2;
                ldsm_x4(Br[ni], addr);
            }
#pragma unroll
            for (int mi = 0; mi < 4; mi++)
#pragma unroll
                for (int j = 0; j < 4; j++)
                    mma_16816_f16(acc[mi][j], Ar[mi],
                                  Br[j >> 1][(j & 1) * 2], Br[j >> 1][(j & 1) * 2 + 1]);
        }
    }

    // epilogue
#pragma unroll
    for (int mi = 0; mi < 4; mi++) {
        const int row0 = rowBase + wm + mi * 16 + (lane >> 2);
#pragma unroll
        for (int j = 0; j < 4; j++) {
            const int col = colBase + wn + j * 8 + (lane & 3) * 2;
            *reinterpret_cast<float2*>(C + (size_t)row0 * N + col) =
                make_float2(acc[mi][j][0], acc[mi][j][1]);
            *reinterpret_cast<float2*>(C + (size_t)(row0 + 8) * N + col) =
                make_float2(acc[mi][j][2], acc[mi][j][3]);
        }
    }
}

// ---------------------------------------------------------------------------
// Fused x->fp16 convert + alpha. Block = 16 rows, 512 threads (16 heads).
// ---------------------------------------------------------------------------
__global__ __launch_bounds__(512) void cvtx_alpha_kernel(
    const float* __restrict__ x, const float* __restrict__ Wa,
    const float* __restrict__ ba, const float* __restrict__ m_gate,
    const float* __restrict__ ascale,
    __half* __restrict__ xh, float* __restrict__ alpha)
{
    extern __shared__ float xs[];        // [16][1024]
    const int tid  = threadIdx.x;
    const int warp = tid >> 5;           // head
    const int lane = tid & 31;
    const int rowBase = blockIdx.x * 16;

    const float4* xg = reinterpret_cast<const float4*>(x + (size_t)rowBase * D_MODEL);
#pragma unroll
    for (int it = 0; it < 8; it++) {
        int i = tid + it * 512;
        float4 v = xg[i];
        reinterpret_cast<float4*>(xs)[i] = v;
        __half2* ph = reinterpret_cast<__half2*>(xh + (size_t)rowBase * D_MODEL + i * 4);
        ph[0] = __half2(__float2half_rn(v.x), __float2half_rn(v.y));
        ph[1] = __half2(__float2half_rn(v.z), __float2half_rn(v.w));
    }
    __syncthreads();

    float wa[32];
#pragma unroll
    for (int i = 0; i < 32; i++)
        wa[i] = Wa[(size_t)warp * D_MODEL + i * 32 + lane];
    const float bw = ba[warp];

#pragma unroll 4
    for (int row = 0; row < 16; row++) {
        const float* xr = xs + row * D_MODEL;
        float s = 0.0f;
#pragma unroll
        for (int i = 0; i < 32; i++)
            s = fmaf(wa[i], xr[i * 32 + lane], s);
#pragma unroll
        for (int off = 16; off; off >>= 1)
            s += __shfl_xor_sync(0xFFFFFFFFu, s, off);
        if (lane == 0) {
            const int r = rowBase + row;
            float sg = __fdividef(1.0f, 1.0f + __expf(-(s + bw)));
            float a = sg * m_gate[r] * ascale[(size_t)r * N_HEADS + warp];
            alpha[(size_t)r * N_HEADS + warp] = fminf(a, ALPHA_MAX);
        }
    }
}

// ---------------------------------------------------------------------------
// Round all 4 weight matrices to fp16 in one launch. DW = 1<<20 elems each.
// ---------------------------------------------------------------------------
__global__ __launch_bounds__(256) void cvt4_kernel(
    const float* __restrict__ W0, const float* __restrict__ W1,
    const float* __restrict__ W2, const float* __restrict__ W3,
    __half* __restrict__ out)
{
    const int i = blockIdx.x * 256 + threadIdx.x;       // 0 .. 4M-1
    const int sel = i >> 20;
    const int off = i & ((1 << 20) - 1);
    const float* src = (sel == 0) ? W0 : (sel == 1) ? W1 : (sel == 2) ? W2 : W3;
    out[i] = __float2half_rn(src[off]);
}

// ---------------------------------------------------------------------------
// Sequential fast-weight scan; 1 barrier/step; y -> fp16 output.
// Block = (b,h); 64 threads (thread = d).
// ILP: p-partials use ktd = kt*DECAY so state decay moves off the critical
// path (overlaps the shuffle tree); kf accumulated in 4 split chains.
// ---------------------------------------------------------------------------
__global__ __launch_bounds__(64) void scan_kernel(
    const float* __restrict__ q, const float* __restrict__ k,
    const float* __restrict__ v, const float* __restrict__ alpha,
    __half* __restrict__ yh, int T)
{
    const int bh = blockIdx.x;
    const int b = bh / N_HEADS;
    const int h = bh % N_HEADS;
    const int d = threadIdx.x;
    const int warp = d >> 5;
    const int lane = d & 31;

    float U[RANK], Vv[RANK];
#pragma unroll
    for (int r = 0; r < RANK; r++) { U[r] = 0.0f; Vv[r] = 0.0f; }

    __shared__ float  sm_ku[2][16][2];   // [buf][r][warp]
    __shared__ float2 sm_sc[2][2];       // [buf][warp] = (s0,s1) partials

    const int l4 = lane & 15;
    const int rIdx = ((l4 & 1) << 3) | ((l4 & 2) << 1) | ((l4 & 4) >> 1) | ((l4 & 8) >> 3);

    const size_t strideT = (size_t)N_HEADS * D_HEAD;   // 1024
    size_t idx = ((size_t)b * T * N_HEADS + h) * D_HEAD + d;
    const size_t abase = (size_t)b * T * N_HEADS + h;

    float qt = q[idx], kt = k[idx], vt = v[idx];
    float a  = alpha[abase];

    float sp0 = 0.f, sp1 = 0.f;
    float vprev = 0.f, kfprev = 0.f;
    size_t idxprev = idx;

    for (int t = 0; t < T; t++) {
        const int buf = t & 1;
        const size_t nidx = idx + strideT;
        float nq = 0.f, nk = 0.f, nv = 0.f, na = 0.f;
        if (t + 1 < T) {
            nq = q[nidx]; nk = k[nidx]; nv = v[nidx];
            na = alpha[abase + (size_t)(t + 1) * N_HEADS];
        }

        // p partials against pre-decay state (ktd folds the decay in);
        // actual state decay overlaps the shuffle tree below.
        const float ktd = kt * DECAY;
        float p[RANK];
#pragma unroll
        for (int r = 0; r < RANK; r++) p[r] = ktd * U[r];

#pragma unroll
        for (int s = 1, cnt = 8; s <= 8; s <<= 1, cnt >>= 1) {
            const bool hi = (lane & s) != 0;
#pragma unroll
            for (int i = 0; i < cnt; i++) {
                float lo_v = p[i], hi_v = p[i + cnt];
                float send = hi ? lo_v : hi_v;
                float recv = __shfl_xor_sync(0xFFFFFFFFu, send, s);
                p[i] = (hi ? hi_v : lo_v) + recv;
            }
        }
        float vr = p[0] + __shfl_xor_sync(0xFFFFFFFFu, p[0], 16);

        // decay state while the shuffle tree / smem exchange is in flight
#pragma unroll
        for (int r = 0; r < RANK; r++) { U[r] *= DECAY; Vv[r] *= DECAY; }

        sm_ku[buf][rIdx][warp] = vr;
        if (lane == 0) sm_sc[buf][warp] = make_float2(sp0, sp1);
        __syncthreads();

        float ku[RANK];
#pragma unroll
        for (int r = 0; r < RANK; r++) {
            float2 t2 = *reinterpret_cast<const float2*>(&sm_ku[buf][r][0]);
            ku[r] = t2.x + t2.y;
        }

        const float ak = a * kt;
        const float av = a * vt;
        float kfp[4] = {0.f, 0.f, 0.f, 0.f};
#pragma unroll
        for (int r = 0; r < RANK; r++) {
            float u = fmaf(ak, ku[r], U[r]);
            float w = fmaf(av, ku[r], Vv[r]);
            u -= BETA * fminf(fmaxf(u, -1.0f), 1.0f);
            w -= BETA * fminf(fmaxf(w, -1.0f), 1.0f);
            U[r] = u;
            Vv[r] = w;
            kfp[r & 3] = fmaf(u, w, kfp[r & 3]);
        }
        const float kf = (kfp[0] + kfp[1]) + (kfp[2] + kfp[3]);

        if (t > 0) {
            float2 w0 = sm_sc[buf][0];
            float2 w1 = sm_sc[buf][1];
            const float S0 = w0.x + w1.x;
            const float S1 = w0.y + w1.y;
            const float m1 = __fdividef(1.0f, 1.0f + __expf(S0 - S1));
            yh[idxprev] = __float2half_rn((1.0f - m1) * vprev + m1 * kfprev);
        }

        const float qn = qt * 0.125f;
        float s0 = qn * kt;
        float s1 = qn * kf;
#pragma unroll
        for (int off = 16; off; off >>= 1) {
            s0 += __shfl_xor_sync(0xFFFFFFFFu, s0, off);
            s1 += __shfl_xor_sync(0xFFFFFFFFu, s1, off);
        }
        sp0 = s0; sp1 = s1;
        vprev = vt; kfprev = kf; idxprev = idx;

        qt = nq; kt = nk; vt = nv; a = na;
        idx = nidx;
    }

    if (lane == 0) sm_sc[T & 1][warp] = make_float2(sp0, sp1);
    __syncthreads();
    {
        float2 w0 = sm_sc[T & 1][0];
        float2 w1 = sm_sc[T & 1][1];
        const float S0 = w0.x + w1.x;
        const float S1 = w0.y + w1.y;
        const float m1 = __fdividef(1.0f, 1.0f + __expf(S0 - S1));
        yh[idxprev] = __float2half_rn((1.0f - m1) * vprev + m1 * kfprev);
    }
}

// ---------------------------------------------------------------------------
// Launch
// ---------------------------------------------------------------------------
extern "C" void kernel_launch(void* const* d_in, const int* in_sizes, int n_in,
                              void* d_out, int out_size)
{
    const float* x      = (const float*)d_in[0];
    const float* m_gate = (const float*)d_in[1];
    const float* ascale = (const float*)d_in[2];
    const float* Wq     = (const float*)d_in[3];
    const float* Wk     = (const float*)d_in[4];
    const float* Wv     = (const float*)d_in[5];
    const float* Wo     = (const float*)d_in[6];
    const float* Wa     = (const float*)d_in[7];
    const float* ba     = (const float*)d_in[8];
    // d_in[9] = mix_logit: cancels in the 2-way softmax; unused.
    float* out = (float*)d_out;

    const int M = in_sizes[1] > 0 ? in_sizes[1] : BT;  // B*T
    const int T = M / BB;

    __half *xh, *wf, *yh;
    float *dq, *dk, *dv, *da;
    cudaGetSymbolAddress((void**)&xh, g_xh);
    cudaGetSymbolAddress((void**)&wf, g_w);
    cudaGetSymbolAddress((void**)&yh, g_yh);
    cudaGetSymbolAddress((void**)&dq, g_q);
    cudaGetSymbolAddress((void**)&dk, g_k);
    cudaGetSymbolAddress((void**)&dv, g_v);
    cudaGetSymbolAddress((void**)&da, g_alpha);

    const int DW = D_MODEL * D_MODEL;

    static bool attr_set = false;
    if (!attr_set) {
        cudaFuncSetAttribute(gemm_f16,
                             cudaFuncAttributeMaxDynamicSharedMemorySize, GEMM_SMEM_BYTES);
        cudaFuncSetAttribute(cvtx_alpha_kernel,
                             cudaFuncAttributeMaxDynamicSharedMemorySize, 16 * D_MODEL * 4);
        attr_set = true;
    }

    cvtx_alpha_kernel<<<M / 16, 512, 16 * D_MODEL * 4>>>(
        x, Wa, ba, m_gate, ascale, xh, da);

    cvt4_kernel<<<(4 * DW) / 256, 256>>>(Wq, Wk, Wv, Wo, wf);

    dim3 gqkv(D_MODEL / GN, M / GM, 3);
    gemm_f16<<<gqkv, 256, GEMM_SMEM_BYTES>>>(xh, wf, dq, dk, dv, M, D_MODEL, D_MODEL);

    scan_kernel<<<BB * N_HEADS, 64>>>(dq, dk, dv, da, yh, T);

    dim3 go(D_MODEL / GN, M / GM, 1);
    gemm_f16<<<go, 256, GEMM_SMEM_BYTES>>>(yh, wf + (size_t)3 * DW,
                                           out, out, out, M, D_MODEL, D_MODEL);
}